// round 1
// baseline (speedup 1.0000x reference)
#include <cuda_runtime.h>

#define HW   262144      // 512*512
#define NB   8
#define NC   64
#define PPT  4           // pixels per thread
#define TPB  256

__global__ __launch_bounds__(TPB) void color_reduce_kernel(
    const float* __restrict__ x,
    const float* __restrict__ pal,
    float* __restrict__ out)
{
    // sp[k] = (-2*cx, -2*cy, -2*cz, ||c||^2); sc[k] = raw color
    __shared__ float4 sp[NC];
    __shared__ float4 sc[NC];

    int t = threadIdx.x;
    if (t < NC) {
        float r = pal[3 * t + 0];
        float g = pal[3 * t + 1];
        float b = pal[3 * t + 2];
        sp[t] = make_float4(-2.0f * r, -2.0f * g, -2.0f * b,
                            fmaf(r, r, fmaf(g, g, b * b)));
        sc[t] = make_float4(r, g, b, 0.0f);
    }
    __syncthreads();

    int gid = blockIdx.x * TPB + t;          // one thread = 4 consecutive pixels
    int b   = gid >> 16;                     // gid / (HW/PPT), HW/PPT = 65536
    int i   = (gid & 65535) * PPT;           // pixel offset within plane
    size_t base = (size_t)b * (3 * HW) + i;

    float4 px = *(const float4*)(x + base);
    float4 py = *(const float4*)(x + base + HW);
    float4 pz = *(const float4*)(x + base + 2 * HW);

    float bd0 = 3.4e38f, bd1 = 3.4e38f, bd2 = 3.4e38f, bd3 = 3.4e38f;
    int   bi0 = 0, bi1 = 0, bi2 = 0, bi3 = 0;

    #pragma unroll 16
    for (int k = 0; k < NC; ++k) {
        float4 c = sp[k];
        // d = ||c||^2 - 2 p.c   (same argmin as ||p-c||^2; ||p||^2 constant per pixel)
        float d0 = fmaf(px.x, c.x, fmaf(py.x, c.y, fmaf(pz.x, c.z, c.w)));
        float d1 = fmaf(px.y, c.x, fmaf(py.y, c.y, fmaf(pz.y, c.z, c.w)));
        float d2 = fmaf(px.z, c.x, fmaf(py.z, c.y, fmaf(pz.z, c.z, c.w)));
        float d3 = fmaf(px.w, c.x, fmaf(py.w, c.y, fmaf(pz.w, c.z, c.w)));
        if (d0 < bd0) { bd0 = d0; bi0 = k; }   // strict < keeps first-min (matches argmin)
        if (d1 < bd1) { bd1 = d1; bi1 = k; }
        if (d2 < bd2) { bd2 = d2; bi2 = k; }
        if (d3 < bd3) { bd3 = d3; bi3 = k; }
    }

    float4 c0 = sc[bi0];
    float4 c1 = sc[bi1];
    float4 c2 = sc[bi2];
    float4 c3 = sc[bi3];

    *(float4*)(out + base)          = make_float4(c0.x, c1.x, c2.x, c3.x);
    *(float4*)(out + base + HW)     = make_float4(c0.y, c1.y, c2.y, c3.y);
    *(float4*)(out + base + 2 * HW) = make_float4(c0.z, c1.z, c2.z, c3.z);
}

extern "C" void kernel_launch(void* const* d_in, const int* in_sizes, int n_in,
                              void* d_out, int out_size)
{
    const float* x   = (const float*)d_in[0];
    const float* pal = (const float*)d_in[1];
    float*       out = (float*)d_out;

    int total_threads = NB * HW / PPT;       // 524288
    color_reduce_kernel<<<total_threads / TPB, TPB>>>(x, pal, out);
}